// round 2
// baseline (speedup 1.0000x reference)
#include <cuda_runtime.h>

// ---------------------------------------------------------------------------
// RegionHead: pool-first reformulation.
//   x: (16,2048,8,14,14) f32   boxes: (16,8,4,4)   cat: (16,4) i32
//   conv5_w: (512,2048)  re_w: (4608,512) re_b: (512)
//   oc1_w:(512,512) oc1_b:(512) oc2_w:(512,301) oc2_b:(301)
//   pr1_w:(512,512) pr1_b:(512) pr2_w:(512,174) pr2_b:(174)
// Output (float32, concatenated): cls_out(16*174) | obj_cls(32*301) | labels(32)
//
// Key identity: ROI-align is linear in the feature map, and the feature map is
// a per-pixel linear map of x (1x1x1 conv). They commute: pool x first
// (4608x2048), then one small GEMM (4608x2048x512) instead of the full-frame
// conv (25088x2048x512). 5.4x fewer FLOPs.
// ---------------------------------------------------------------------------

#define FRAMES 128          // B*T
#define CIN    2048
#define CI     512
#define CELLS  36           // NB(4) * PH*PW(9)
#define ROWS1  (FRAMES*CELLS)   // 4608
#define K2     4608         // 9*512

// scratch (device globals; no allocation allowed)
__device__ float g_pooledx[ROWS1*CIN];     // (frame,cell) x cin
__device__ float g_rois2[ROWS1*CI];        // (frame,cell) x cout == A2(512x4608)
__device__ float g_regpart[8*512*512];     // split-K partials
__device__ float g_reg[512*512];           // relu(feats@re_w + b)
__device__ float g_regmean[64*512];        // (b,nb) x 512
__device__ float g_pooled[16*512];
__device__ float g_objfeas[32*512];
__device__ float g_h1[32*512];
__device__ float g_h2[16*512];
__device__ int   g_tapidx[ROWS1*16];
__device__ float g_tapw[ROWS1*16];

// ---------------------------------------------------------------------------
// 1) ROI-align tap tables: per (frame,box,cell) 16 (pixel,weight) taps
// ---------------------------------------------------------------------------
__global__ void taps_kernel(const float* __restrict__ boxes)
{
    int id = threadIdx.x;            // 0..511  == frame*4+box
    if (id >= 512) return;
    int frame = id >> 2;
    int box   = id & 3;
    float cx = boxes[id*4+0], cy = boxes[id*4+1];
    float w_ = boxes[id*4+2], h_ = boxes[id*4+3];
    // ((c +- wh/2)*224) * (14/224)
    float x1 = ((cx - w_*0.5f)*224.0f)*0.0625f;
    float y1 = ((cy - h_*0.5f)*224.0f)*0.0625f;
    float x2 = ((cx + w_*0.5f)*224.0f)*0.0625f;
    float y2 = ((cy + h_*0.5f)*224.0f)*0.0625f;
    float roiw = fmaxf(x2-x1, 1.0f);
    float roih = fmaxf(y2-y1, 1.0f);
    float bw = roiw/3.0f;
    float bh = roih/3.0f;
    for (int ph = 0; ph < 3; ph++) {
        for (int pw = 0; pw < 3; pw++) {
            int cellg = box*9 + ph*3 + pw;
            int base  = (frame*CELLS + cellg)*16;
            for (int sy = 0; sy < 2; sy++) {
                for (int sx = 0; sx < 2; sx++) {
                    float y = y1 + (float)ph*bh + (sy+0.5f)*bh*0.5f;
                    float x = x1 + (float)pw*bw + (sx+0.5f)*bw*0.5f;
                    bool valid = (y > -1.0f) && (y < 14.0f) && (x > -1.0f) && (x < 14.0f);
                    float wv = valid ? 0.25f : 0.0f;    // 1/(SR*SR) average
                    float yc = fminf(fmaxf(y, 0.0f), 13.0f);
                    float xc = fminf(fmaxf(x, 0.0f), 13.0f);
                    int y0 = (int)floorf(yc);
                    int x0 = (int)floorf(xc);
                    int y1i = min(y0+1, 13);
                    int x1i = min(x0+1, 13);
                    float ly = yc - (float)y0, lx = xc - (float)x0;
                    float hy = 1.0f - ly,      hx = 1.0f - lx;
                    int j = base + (sy*2+sx)*4;
                    g_tapidx[j+0] = y0*14 + x0;   g_tapw[j+0] = hy*hx*wv;
                    g_tapidx[j+1] = y0*14 + x1i;  g_tapw[j+1] = hy*lx*wv;
                    g_tapidx[j+2] = y1i*14 + x0;  g_tapw[j+2] = ly*hx*wv;
                    g_tapidx[j+3] = y1i*14 + x1i; g_tapw[j+3] = ly*lx*wv;
                }
            }
        }
    }
}

// ---------------------------------------------------------------------------
// 2) Pool raw x -> pooledx  (streams all of x once, 205 MB)
//    grid (frame=128, part=4), 256 threads; 16 chunks of 32 channels;
//    smem transposed [pixel][chan] so compute uses conflict-light LDS.128.
// ---------------------------------------------------------------------------
__global__ __launch_bounds__(256) void pool_kernel(const float* __restrict__ x)
{
    __shared__ __align__(16) float sxt[196*36];   // [pixel][32ch + 4 pad]
    __shared__ int   sti[576];
    __shared__ float stw[576];
    int frame = blockIdx.x;
    int part  = blockIdx.y;
    int tid   = threadIdx.x;
    int b = frame >> 3, t = frame & 7;
    for (int i = tid; i < 576; i += 256) {
        sti[i] = g_tapidx[frame*576 + i];
        stw[i] = g_tapw[frame*576 + i];
    }
    const float* xb = x + (size_t)b*CIN*1568 + (size_t)t*196;
    float* outb = g_pooledx + (size_t)frame*CELLS*CIN;

    for (int chunk = 0; chunk < 16; chunk++) {
        int c0 = part*512 + chunk*32;
        __syncthreads();
        // load 32 channels x 196 pixels (float4), transpose into sxt
        for (int i = tid; i < 32*49; i += 256) {
            int r = i / 49;
            int q = i - r*49;
            float4 v = *(const float4*)(xb + (size_t)(c0+r)*1568 + q*4);
            int p = q*4;
            sxt[(p+0)*36 + r] = v.x;
            sxt[(p+1)*36 + r] = v.y;
            sxt[(p+2)*36 + r] = v.z;
            sxt[(p+3)*36 + r] = v.w;
        }
        __syncthreads();
        // 36 cells x 8 channel-quads
        for (int i = tid; i < 288; i += 256) {
            int cl4 = i & 7;
            int cg  = i >> 3;
            const int*   ti = &sti[cg*16];
            const float* tw = &stw[cg*16];
            float4 acc = make_float4(0.f, 0.f, 0.f, 0.f);
            #pragma unroll
            for (int j = 0; j < 16; j++) {
                float w = tw[j];
                float4 v = *(const float4*)&sxt[ti[j]*36 + cl4*4];
                acc.x += w*v.x; acc.y += w*v.y; acc.z += w*v.z; acc.w += w*v.w;
            }
            *(float4*)(outb + (size_t)cg*CIN + c0 + cl4*4) = acc;
        }
    }
}

// ---------------------------------------------------------------------------
// 3) GEMM1: rois2(4608x512) = pooledx(4608x2048) @ conv5_w(512x2048)^T
//    fp32 SIMT, 128x128x16 tiles, 8x8 per thread. Sizes divide exactly.
// ---------------------------------------------------------------------------
__global__ __launch_bounds__(256) void gemm1_kernel(const float* __restrict__ Bw)
{
    __shared__ __align__(16) float As[16][128];
    __shared__ __align__(16) float Bs[16][128];
    const int K = 2048, N = 512;
    int tid = threadIdx.x;
    int lr = tid >> 2;
    int lc = (tid & 3) << 2;
    const float* Ap = g_pooledx + (size_t)(blockIdx.x*128 + lr)*K + lc;
    const float* Bp = Bw        + (size_t)(blockIdx.y*128 + lr)*K + lc;
    float acc[8][8];
    #pragma unroll
    for (int i = 0; i < 8; i++)
        #pragma unroll
        for (int j = 0; j < 8; j++) acc[i][j] = 0.0f;
    int tx = tid & 15, ty = tid >> 4;

    for (int k0 = 0; k0 < K; k0 += 16) {
        float4 a0 = *(const float4*)(Ap + k0);
        float4 a1 = *(const float4*)(Ap + (size_t)64*K + k0);
        float4 b0 = *(const float4*)(Bp + k0);
        float4 b1 = *(const float4*)(Bp + (size_t)64*K + k0);
        As[lc+0][lr]    = a0.x; As[lc+1][lr]    = a0.y; As[lc+2][lr]    = a0.z; As[lc+3][lr]    = a0.w;
        As[lc+0][lr+64] = a1.x; As[lc+1][lr+64] = a1.y; As[lc+2][lr+64] = a1.z; As[lc+3][lr+64] = a1.w;
        Bs[lc+0][lr]    = b0.x; Bs[lc+1][lr]    = b0.y; Bs[lc+2][lr]    = b0.z; Bs[lc+3][lr]    = b0.w;
        Bs[lc+0][lr+64] = b1.x; Bs[lc+1][lr+64] = b1.y; Bs[lc+2][lr+64] = b1.z; Bs[lc+3][lr+64] = b1.w;
        __syncthreads();
        #pragma unroll
        for (int kk = 0; kk < 16; kk++) {
            float4 av0 = *(const float4*)&As[kk][ty*8];
            float4 av1 = *(const float4*)&As[kk][ty*8+4];
            float4 bv0 = *(const float4*)&Bs[kk][tx*8];
            float4 bv1 = *(const float4*)&Bs[kk][tx*8+4];
            float a[8] = {av0.x,av0.y,av0.z,av0.w,av1.x,av1.y,av1.z,av1.w};
            float bb[8]= {bv0.x,bv0.y,bv0.z,bv0.w,bv1.x,bv1.y,bv1.z,bv1.w};
            #pragma unroll
            for (int i = 0; i < 8; i++)
                #pragma unroll
                for (int j = 0; j < 8; j++) acc[i][j] += a[i]*bb[j];
        }
        __syncthreads();
    }
    float* Cp = g_rois2 + (size_t)(blockIdx.x*128 + ty*8)*N + blockIdx.y*128 + tx*8;
    #pragma unroll
    for (int i = 0; i < 8; i++) {
        *(float4*)(Cp + (size_t)i*N)     = make_float4(acc[i][0],acc[i][1],acc[i][2],acc[i][3]);
        *(float4*)(Cp + (size_t)i*N + 4) = make_float4(acc[i][4],acc[i][5],acc[i][6],acc[i][7]);
    }
}

// ---------------------------------------------------------------------------
// 4) GEMM2 (split-K=8): regpart[s] = A2(512x4608 chunk) @ B2(4608x512 chunk)
//    A2 = g_rois2 viewed as (512 x 4608) row-major (exact layout identity).
//    B2[k][n] = re_w[(ci*9+cell)*512 + n],  k = cell*512+ci  (row remap).
// ---------------------------------------------------------------------------
__global__ __launch_bounds__(256) void gemm2_kernel(const float* __restrict__ W)
{
    __shared__ __align__(16) float As[16][128];
    __shared__ __align__(16) float Bs[16][128];
    int tid = threadIdx.x;
    int lr = tid >> 2;
    int lc = (tid & 3) << 2;
    int kl = tid >> 4;            // 0..15  (k row within tile)
    int nl = (tid & 15) << 3;     // 0..120 (n offset, step 8)
    int bn = blockIdx.y*128;
    int kS = blockIdx.z*576;
    const float* Ap = g_rois2 + (size_t)(blockIdx.x*128 + lr)*K2 + lc;
    float acc[8][8];
    #pragma unroll
    for (int i = 0; i < 8; i++)
        #pragma unroll
        for (int j = 0; j < 8; j++) acc[i][j] = 0.0f;
    int tx = tid & 15, ty = tid >> 4;

    for (int k0 = kS; k0 < kS + 576; k0 += 16) {
        float4 a0 = *(const float4*)(Ap + k0);
        float4 a1 = *(const float4*)(Ap + (size_t)64*K2 + k0);
        int kg = k0 + kl;
        int co = kg & 511;        // ci
        int cell = kg >> 9;       // 0..8
        const float* wr = W + (size_t)(co*9 + cell)*512 + bn + nl;
        float4 b0 = *(const float4*)wr;
        float4 b1 = *(const float4*)(wr + 4);
        As[lc+0][lr]    = a0.x; As[lc+1][lr]    = a0.y; As[lc+2][lr]    = a0.z; As[lc+3][lr]    = a0.w;
        As[lc+0][lr+64] = a1.x; As[lc+1][lr+64] = a1.y; As[lc+2][lr+64] = a1.z; As[lc+3][lr+64] = a1.w;
        *(float4*)&Bs[kl][nl]     = b0;
        *(float4*)&Bs[kl][nl + 4] = b1;
        __syncthreads();
        #pragma unroll
        for (int kk = 0; kk < 16; kk++) {
            float4 av0 = *(const float4*)&As[kk][ty*8];
            float4 av1 = *(const float4*)&As[kk][ty*8+4];
            float4 bv0 = *(const float4*)&Bs[kk][tx*8];
            float4 bv1 = *(const float4*)&Bs[kk][tx*8+4];
            float a[8] = {av0.x,av0.y,av0.z,av0.w,av1.x,av1.y,av1.z,av1.w};
            float bb[8]= {bv0.x,bv0.y,bv0.z,bv0.w,bv1.x,bv1.y,bv1.z,bv1.w};
            #pragma unroll
            for (int i = 0; i < 8; i++)
                #pragma unroll
                for (int j = 0; j < 8; j++) acc[i][j] += a[i]*bb[j];
        }
        __syncthreads();
    }
    float* Cp = g_regpart + (size_t)blockIdx.z*262144
              + (size_t)(blockIdx.x*128 + ty*8)*512 + bn + tx*8;
    #pragma unroll
    for (int i = 0; i < 8; i++) {
        *(float4*)(Cp + (size_t)i*512)     = make_float4(acc[i][0],acc[i][1],acc[i][2],acc[i][3]);
        *(float4*)(Cp + (size_t)i*512 + 4) = make_float4(acc[i][4],acc[i][5],acc[i][6],acc[i][7]);
    }
}

// 5) split-K reduce + bias + relu
__global__ void reduce_relu_kernel(const float* __restrict__ reb)
{
    int idx = blockIdx.x*256 + threadIdx.x;      // < 262144
    float v = reb[idx & 511];
    #pragma unroll
    for (int s = 0; s < 8; s++) v += g_regpart[(size_t)s*262144 + idx];
    g_reg[idx] = fmaxf(v, 0.0f);
}

// 6) mean over T: regmean[(b*4+nb)*512+o]
__global__ void regmean_kernel()
{
    int idx = blockIdx.x*256 + threadIdx.x;      // < 32768
    int bnb = idx >> 9;
    int o   = idx & 511;
    int b = bnb >> 2, nb = bnb & 3;
    float s = 0.0f;
    #pragma unroll
    for (int t = 0; t < 8; t++) s += g_reg[(size_t)((b*8 + t)*4 + nb)*512 + o];
    g_regmean[idx] = s * 0.125f;
}

// 7) pooled = mean over NB; objfeas = rows nb=2,3
//    (argsort of the all-equal keys (cat==0 is always false) is [0,1])
__global__ void post2_kernel()
{
    int idx = blockIdx.x*256 + threadIdx.x;      // < 24576
    if (idx < 8192) {
        int b = idx >> 9, o = idx & 511;
        float s = 0.0f;
        #pragma unroll
        for (int nb = 0; nb < 4; nb++) s += g_regmean[(b*4 + nb)*512 + o];
        g_pooled[idx] = s * 0.25f;
    } else if (idx < 24576) {
        int j = idx - 8192;
        int r = j >> 9, o = j & 511;
        int b = r >> 1, jj = r & 1;
        g_objfeas[j] = g_regmean[(b*4 + 2 + jj)*512 + o];
    }
}

// 8) small head GEMM: C[row][n] = bias[n] + sum_k A[row][k]*W[k][n]   (K=512)
//    which: 0 objfeas->h1  1 h1->outC  2 pooled->h2  3 h2->outC
//    (A/C resolved from device globals to keep kernel_launch launch-only)
__global__ __launch_bounds__(128) void head_gemm(int which,
                                                 const float* __restrict__ W,
                                                 const float* __restrict__ bias,
                                                 float* __restrict__ outC, int N)
{
    const float* A;
    float* C;
    switch (which) {
        case 0:  A = g_objfeas; C = g_h1;  break;
        case 1:  A = g_h1;      C = outC;  break;
        case 2:  A = g_pooled;  C = g_h2;  break;
        default: A = g_h2;      C = outC;  break;
    }
    __shared__ float As[512];
    int row = blockIdx.x;
    for (int k = threadIdx.x; k < 512; k += 128) As[k] = A[(size_t)row*512 + k];
    __syncthreads();
    int n = blockIdx.y*128 + threadIdx.x;
    if (n < N) {
        float acc = bias[n];
        #pragma unroll 8
        for (int k = 0; k < 512; k++) acc += As[k]*W[(size_t)k*N + n];
        C[(size_t)row*N + n] = acc;
    }
}

// 9) labels: obj_category[:, 2:4] flattened, as float
__global__ void labels_kernel(const int* __restrict__ cat, float* __restrict__ out)
{
    int i = threadIdx.x;   // 32
    out[i] = (float)cat[(i >> 1)*4 + 2 + (i & 1)];
}

// ---------------------------------------------------------------------------
extern "C" void kernel_launch(void* const* d_in, const int* in_sizes, int n_in,
                              void* d_out, int out_size)
{
    (void)in_sizes; (void)n_in; (void)out_size;
    const float* x       = (const float*)d_in[0];
    const float* boxes   = (const float*)d_in[1];
    const int*   cat     = (const int*)  d_in[2];
    const float* conv5_w = (const float*)d_in[3];
    const float* re_w    = (const float*)d_in[4];
    const float* re_b    = (const float*)d_in[5];
    const float* oc1_w   = (const float*)d_in[6];
    const float* oc1_b   = (const float*)d_in[7];
    const float* oc2_w   = (const float*)d_in[8];
    const float* oc2_b   = (const float*)d_in[9];
    const float* pr1_w   = (const float*)d_in[10];
    const float* pr1_b   = (const float*)d_in[11];
    const float* pr2_w   = (const float*)d_in[12];
    const float* pr2_b   = (const float*)d_in[13];
    float* out = (float*)d_out;

    taps_kernel<<<1, 512>>>(boxes);
    pool_kernel<<<dim3(128, 4), 256>>>(x);
    gemm1_kernel<<<dim3(36, 4), 256>>>(conv5_w);          // 4608x2048x512
    gemm2_kernel<<<dim3(4, 4, 8), 256>>>(re_w);           // 512x4608x512 splitK
    reduce_relu_kernel<<<1024, 256>>>(re_b);
    regmean_kernel<<<128, 256>>>();
    post2_kernel<<<96, 256>>>();
    head_gemm<<<dim3(32, 4), 128>>>(0, oc1_w, oc1_b, nullptr,     512);
    head_gemm<<<dim3(32, 3), 128>>>(1, oc2_w, oc2_b, out + 2784,  301);
    head_gemm<<<dim3(16, 4), 128>>>(2, pr1_w, pr1_b, nullptr,     512);
    head_gemm<<<dim3(16, 2), 128>>>(3, pr2_w, pr2_b, out,         174);
    labels_kernel<<<1, 32>>>(cat, out + 12416);
}

// round 4
// speedup vs baseline: 1.1769x; 1.1769x over previous
#include <cuda_runtime.h>

// ---------------------------------------------------------------------------
// RegionHead: pool-first reformulation.
// ROI-align is linear in the feature map; the feature map is a per-pixel
// linear map of x (1x1x1 conv). They commute: pool x first (4608x2048), then
// GEMM1 (4608x2048x512) instead of the full-frame conv (25088x2048x512).
// Output (float32): cls_out(16*174) | obj_cls(32*301) | labels(32)
// ---------------------------------------------------------------------------

#define FRAMES 128          // B*T
#define CIN    2048
#define CI     512
#define CELLS  36           // NB(4) * PH*PW(9)
#define ROWS1  (FRAMES*CELLS)   // 4608
#define K2     4608         // 9*512
#define SPLITK 9
#define SPAD   132          // padded smem row (132*4B = 16B-aligned, 2-way max)

// scratch (device globals; no allocation allowed)
__device__ float g_pooledx[ROWS1*CIN];       // (frame,cell) x cin
__device__ float g_rois2[ROWS1*CI];          // (frame,cell) x cout == A2(512x4608)
__device__ float g_regpart[SPLITK*512*512];  // split-K partials
__device__ float g_reg[512*512];             // relu(feats@re_w + b)
__device__ float g_regmean[64*512];          // (b,nb) x 512
__device__ float g_pooled[16*512];
__device__ float g_objfeas[32*512];
__device__ float g_h1[32*512];
__device__ float g_h2[16*512];
__device__ int   g_tapidx[ROWS1*16];
__device__ float g_tapw[ROWS1*16];

// ---------------------------------------------------------------------------
// 1) ROI-align tap tables: per (frame,box,cell) 16 (pixel,weight) taps
// ---------------------------------------------------------------------------
__global__ void taps_kernel(const float* __restrict__ boxes)
{
    int id = threadIdx.x;            // 0..511  == frame*4+box
    if (id >= 512) return;
    int frame = id >> 2;
    int box   = id & 3;
    float cx = boxes[id*4+0], cy = boxes[id*4+1];
    float w_ = boxes[id*4+2], h_ = boxes[id*4+3];
    float x1 = ((cx - w_*0.5f)*224.0f)*0.0625f;
    float y1 = ((cy - h_*0.5f)*224.0f)*0.0625f;
    float x2 = ((cx + w_*0.5f)*224.0f)*0.0625f;
    float y2 = ((cy + h_*0.5f)*224.0f)*0.0625f;
    float roiw = fmaxf(x2-x1, 1.0f);
    float roih = fmaxf(y2-y1, 1.0f);
    float bw = roiw/3.0f;
    float bh = roih/3.0f;
    for (int ph = 0; ph < 3; ph++) {
        for (int pw = 0; pw < 3; pw++) {
            int cellg = box*9 + ph*3 + pw;
            int base  = (frame*CELLS + cellg)*16;
            for (int sy = 0; sy < 2; sy++) {
                for (int sx = 0; sx < 2; sx++) {
                    float y = y1 + (float)ph*bh + (sy+0.5f)*bh*0.5f;
                    float x = x1 + (float)pw*bw + (sx+0.5f)*bw*0.5f;
                    bool valid = (y > -1.0f) && (y < 14.0f) && (x > -1.0f) && (x < 14.0f);
                    float wv = valid ? 0.25f : 0.0f;
                    float yc = fminf(fmaxf(y, 0.0f), 13.0f);
                    float xc = fminf(fmaxf(x, 0.0f), 13.0f);
                    int y0 = (int)floorf(yc);
                    int x0 = (int)floorf(xc);
                    int y1i = min(y0+1, 13);
                    int x1i = min(x0+1, 13);
                    float ly = yc - (float)y0, lx = xc - (float)x0;
                    float hy = 1.0f - ly,      hx = 1.0f - lx;
                    int j = base + (sy*2+sx)*4;
                    g_tapidx[j+0] = y0*14 + x0;   g_tapw[j+0] = hy*hx*wv;
                    g_tapidx[j+1] = y0*14 + x1i;  g_tapw[j+1] = hy*lx*wv;
                    g_tapidx[j+2] = y1i*14 + x0;  g_tapw[j+2] = ly*hx*wv;
                    g_tapidx[j+3] = y1i*14 + x1i; g_tapw[j+3] = ly*lx*wv;
                }
            }
        }
    }
}

// ---------------------------------------------------------------------------
// 2) Pool raw x -> pooledx  (streams all of x once, 205 MB)
// ---------------------------------------------------------------------------
__global__ __launch_bounds__(256) void pool_kernel(const float* __restrict__ x)
{
    __shared__ __align__(16) float sxt[196*36];
    __shared__ int   sti[576];
    __shared__ float stw[576];
    int frame = blockIdx.x;
    int part  = blockIdx.y;
    int tid   = threadIdx.x;
    int b = frame >> 3, t = frame & 7;
    for (int i = tid; i < 576; i += 256) {
        sti[i] = g_tapidx[frame*576 + i];
        stw[i] = g_tapw[frame*576 + i];
    }
    const float* xb = x + (size_t)b*CIN*1568 + (size_t)t*196;
    float* outb = g_pooledx + (size_t)frame*CELLS*CIN;

    for (int chunk = 0; chunk < 16; chunk++) {
        int c0 = part*512 + chunk*32;
        __syncthreads();
        for (int i = tid; i < 32*49; i += 256) {
            int r = i / 49;
            int q = i - r*49;
            float4 v = *(const float4*)(xb + (size_t)(c0+r)*1568 + q*4);
            int p = q*4;
            sxt[(p+0)*36 + r] = v.x;
            sxt[(p+1)*36 + r] = v.y;
            sxt[(p+2)*36 + r] = v.z;
            sxt[(p+3)*36 + r] = v.w;
        }
        __syncthreads();
        for (int i = tid; i < 288; i += 256) {
            int cl4 = i & 7;
            int cg  = i >> 3;
            const int*   ti = &sti[cg*16];
            const float* tw = &stw[cg*16];
            float4 acc = make_float4(0.f, 0.f, 0.f, 0.f);
            #pragma unroll
            for (int j = 0; j < 16; j++) {
                float w = tw[j];
                float4 v = *(const float4*)&sxt[ti[j]*36 + cl4*4];
                acc.x += w*v.x; acc.y += w*v.y; acc.z += w*v.z; acc.w += w*v.w;
            }
            *(float4*)(outb + (size_t)cg*CIN + c0 + cl4*4) = acc;
        }
    }
}

// ---------------------------------------------------------------------------
// 3) GEMM1: rois2(4608x512) = pooledx(4608x2048) @ conv5_w(512x2048)^T
//    128x128x16 tiles, 8x8/thread, double-buffered smem + register prefetch,
//    ONE __syncthreads per k-tile.
// ---------------------------------------------------------------------------
__global__ __launch_bounds__(256) void gemm1_kernel(const float* __restrict__ Bw)
{
    __shared__ __align__(16) float As[2][16][SPAD];
    __shared__ __align__(16) float Bs[2][16][SPAD];
    const int K = 2048, N = 512, NT = K/16;
    int tid = threadIdx.x;
    int lr = tid >> 2;          // 0..63
    int lc = (tid & 3) << 2;    // 0,4,8,12
    const float* Ap = g_pooledx + (size_t)(blockIdx.x*128 + lr)*K + lc;
    const float* Bp = Bw        + (size_t)(blockIdx.y*128 + lr)*K + lc;
    float acc[8][8];
    #pragma unroll
    for (int i = 0; i < 8; i++)
        #pragma unroll
        for (int j = 0; j < 8; j++) acc[i][j] = 0.0f;
    int tx = tid & 15, ty = tid >> 4;

    float4 pa0 = *(const float4*)(Ap);
    float4 pa1 = *(const float4*)(Ap + (size_t)64*K);
    float4 pb0 = *(const float4*)(Bp);
    float4 pb1 = *(const float4*)(Bp + (size_t)64*K);
    As[0][lc+0][lr]    = pa0.x; As[0][lc+1][lr]    = pa0.y; As[0][lc+2][lr]    = pa0.z; As[0][lc+3][lr]    = pa0.w;
    As[0][lc+0][lr+64] = pa1.x; As[0][lc+1][lr+64] = pa1.y; As[0][lc+2][lr+64] = pa1.z; As[0][lc+3][lr+64] = pa1.w;
    Bs[0][lc+0][lr]    = pb0.x; Bs[0][lc+1][lr]    = pb0.y; Bs[0][lc+2][lr]    = pb0.z; Bs[0][lc+3][lr]    = pb0.w;
    Bs[0][lc+0][lr+64] = pb1.x; Bs[0][lc+1][lr+64] = pb1.y; Bs[0][lc+2][lr+64] = pb1.z; Bs[0][lc+3][lr+64] = pb1.w;
    __syncthreads();

    int cur = 0;
    for (int kt = 1; kt <= NT; kt++) {
        const bool more = (kt < NT);
        if (more) {
            int k0 = kt*16;
            pa0 = *(const float4*)(Ap + k0);
            pa1 = *(const float4*)(Ap + (size_t)64*K + k0);
            pb0 = *(const float4*)(Bp + k0);
            pb1 = *(const float4*)(Bp + (size_t)64*K + k0);
        }
        #pragma unroll
        for (int kk = 0; kk < 16; kk++) {
            float4 av0 = *(const float4*)&As[cur][kk][ty*8];
            float4 av1 = *(const float4*)&As[cur][kk][ty*8+4];
            float4 bv0 = *(const float4*)&Bs[cur][kk][tx*8];
            float4 bv1 = *(const float4*)&Bs[cur][kk][tx*8+4];
            float a[8] = {av0.x,av0.y,av0.z,av0.w,av1.x,av1.y,av1.z,av1.w};
            float bb[8]= {bv0.x,bv0.y,bv0.z,bv0.w,bv1.x,bv1.y,bv1.z,bv1.w};
            #pragma unroll
            for (int i = 0; i < 8; i++)
                #pragma unroll
                for (int j = 0; j < 8; j++) acc[i][j] += a[i]*bb[j];
        }
        if (more) {
            int nx = cur ^ 1;
            As[nx][lc+0][lr]    = pa0.x; As[nx][lc+1][lr]    = pa0.y; As[nx][lc+2][lr]    = pa0.z; As[nx][lc+3][lr]    = pa0.w;
            As[nx][lc+0][lr+64] = pa1.x; As[nx][lc+1][lr+64] = pa1.y; As[nx][lc+2][lr+64] = pa1.z; As[nx][lc+3][lr+64] = pa1.w;
            Bs[nx][lc+0][lr]    = pb0.x; Bs[nx][lc+1][lr]    = pb0.y; Bs[nx][lc+2][lr]    = pb0.z; Bs[nx][lc+3][lr]    = pb0.w;
            Bs[nx][lc+0][lr+64] = pb1.x; Bs[nx][lc+1][lr+64] = pb1.y; Bs[nx][lc+2][lr+64] = pb1.z; Bs[nx][lc+3][lr+64] = pb1.w;
        }
        __syncthreads();
        cur ^= 1;
    }
    float* Cp = g_rois2 + (size_t)(blockIdx.x*128 + ty*8)*N + blockIdx.y*128 + tx*8;
    #pragma unroll
    for (int i = 0; i < 8; i++) {
        *(float4*)(Cp + (size_t)i*N)     = make_float4(acc[i][0],acc[i][1],acc[i][2],acc[i][3]);
        *(float4*)(Cp + (size_t)i*N + 4) = make_float4(acc[i][4],acc[i][5],acc[i][6],acc[i][7]);
    }
}

// ---------------------------------------------------------------------------
// 4) GEMM2 (split-K=9, chunk 512): regpart[z] = A2 chunk @ B2 chunk
//    A2 = g_rois2 viewed as (512 x 4608) row-major (layout identity).
//    B2[k][n] = re_w[(ci*9+cell)*512 + n],  k = cell*512+ci (row remap; B tile
//    is already [k][n] so no transpose on store).
// ---------------------------------------------------------------------------
__global__ __launch_bounds__(256) void gemm2_kernel(const float* __restrict__ W)
{
    __shared__ __align__(16) float As[2][16][SPAD];
    __shared__ __align__(16) float Bs[2][16][SPAD];
    const int NT = 32;            // 512 / 16
    int tid = threadIdx.x;
    int lr = tid >> 2;
    int lc = (tid & 3) << 2;
    int kl = tid >> 4;            // 0..15  (k row within tile)
    int nl = (tid & 15) << 3;     // 0..120 (n offset, step 8)
    int bn = blockIdx.y*128;
    int kS = blockIdx.z*512;
    const float* Ap = g_rois2 + (size_t)(blockIdx.x*128 + lr)*K2 + lc + kS;
    float acc[8][8];
    #pragma unroll
    for (int i = 0; i < 8; i++)
        #pragma unroll
        for (int j = 0; j < 8; j++) acc[i][j] = 0.0f;
    int tx = tid & 15, ty = tid >> 4;

    // prefetch tile 0
    float4 pa0 = *(const float4*)(Ap);
    float4 pa1 = *(const float4*)(Ap + (size_t)64*K2);
    int kg0 = kS + kl;
    const float* wr0 = W + (size_t)((kg0 & 511)*9 + (kg0 >> 9))*512 + bn + nl;
    float4 pb0 = *(const float4*)wr0;
    float4 pb1 = *(const float4*)(wr0 + 4);
    As[0][lc+0][lr]    = pa0.x; As[0][lc+1][lr]    = pa0.y; As[0][lc+2][lr]    = pa0.z; As[0][lc+3][lr]    = pa0.w;
    As[0][lc+0][lr+64] = pa1.x; As[0][lc+1][lr+64] = pa1.y; As[0][lc+2][lr+64] = pa1.z; As[0][lc+3][lr+64] = pa1.w;
    *(float4*)&Bs[0][kl][nl]     = pb0;
    *(float4*)&Bs[0][kl][nl + 4] = pb1;
    __syncthreads();

    int cur = 0;
    for (int kt = 1; kt <= NT; kt++) {
        const bool more = (kt < NT);
        if (more) {
            int k0 = kt*16;
            pa0 = *(const float4*)(Ap + k0);
            pa1 = *(const float4*)(Ap + (size_t)64*K2 + k0);
            int kg = kS + k0 + kl;
            const float* wr = W + (size_t)((kg & 511)*9 + (kg >> 9))*512 + bn + nl;
            pb0 = *(const float4*)wr;
            pb1 = *(const float4*)(wr + 4);
        }
        #pragma unroll
        for (int kk = 0; kk < 16; kk++) {
            float4 av0 = *(const float4*)&As[cur][kk][ty*8];
            float4 av1 = *(const float4*)&As[cur][kk][ty*8+4];
            float4 bv0 = *(const float4*)&Bs[cur][kk][tx*8];
            float4 bv1 = *(const float4*)&Bs[cur][kk][tx*8+4];
            float a[8] = {av0.x,av0.y,av0.z,av0.w,av1.x,av1.y,av1.z,av1.w};
            float bb[8]= {bv0.x,bv0.y,bv0.z,bv0.w,bv1.x,bv1.y,bv1.z,bv1.w};
            #pragma unroll
            for (int i = 0; i < 8; i++)
                #pragma unroll
                for (int j = 0; j < 8; j++) acc[i][j] += a[i]*bb[j];
        }
        if (more) {
            int nx = cur ^ 1;
            As[nx][lc+0][lr]    = pa0.x; As[nx][lc+1][lr]    = pa0.y; As[nx][lc+2][lr]    = pa0.z; As[nx][lc+3][lr]    = pa0.w;
            As[nx][lc+0][lr+64] = pa1.x; As[nx][lc+1][lr+64] = pa1.y; As[nx][lc+2][lr+64] = pa1.z; As[nx][lc+3][lr+64] = pa1.w;
            *(float4*)&Bs[nx][kl][nl]     = pb0;
            *(float4*)&Bs[nx][kl][nl + 4] = pb1;
        }
        __syncthreads();
        cur ^= 1;
    }
    float* Cp = g_regpart + (size_t)blockIdx.z*262144
              + (size_t)(blockIdx.x*128 + ty*8)*512 + bn + tx*8;
    #pragma unroll
    for (int i = 0; i < 8; i++) {
        *(float4*)(Cp + (size_t)i*512)     = make_float4(acc[i][0],acc[i][1],acc[i][2],acc[i][3]);
        *(float4*)(Cp + (size_t)i*512 + 4) = make_float4(acc[i][4],acc[i][5],acc[i][6],acc[i][7]);
    }
}

// 5) split-K reduce + bias + relu
__global__ void reduce_relu_kernel(const float* __restrict__ reb)
{
    int idx = blockIdx.x*256 + threadIdx.x;      // < 262144
    float v = reb[idx & 511];
    #pragma unroll
    for (int s = 0; s < SPLITK; s++) v += g_regpart[(size_t)s*262144 + idx];
    g_reg[idx] = fmaxf(v, 0.0f);
}

// 6) mean over T
__global__ void regmean_kernel()
{
    int idx = blockIdx.x*256 + threadIdx.x;      // < 32768
    int bnb = idx >> 9;
    int o   = idx & 511;
    int b = bnb >> 2, nb = bnb & 3;
    float s = 0.0f;
    #pragma unroll
    for (int t = 0; t < 8; t++) s += g_reg[(size_t)((b*8 + t)*4 + nb)*512 + o];
    g_regmean[idx] = s * 0.125f;
}

// 7) pooled = mean over NB; objfeas = rows nb=2,3 (argsort of equal keys = [0,1])
__global__ void post2_kernel()
{
    int idx = blockIdx.x*256 + threadIdx.x;      // < 24576
    if (idx < 8192) {
        int b = idx >> 9, o = idx & 511;
        float s = 0.0f;
        #pragma unroll
        for (int nb = 0; nb < 4; nb++) s += g_regmean[(b*4 + nb)*512 + o];
        g_pooled[idx] = s * 0.25f;
    } else if (idx < 24576) {
        int j = idx - 8192;
        int r = j >> 9, o = j & 511;
        int b = r >> 1, jj = r & 1;
        g_objfeas[j] = g_regmean[(b*4 + 2 + jj)*512 + o];
    }
}

// 8) small head GEMM: C[row][n] = bias[n] + sum_k A[row][k]*W[k][n]   (K=512)
__global__ __launch_bounds__(128) void head_gemm(int which,
                                                 const float* __restrict__ W,
                                                 const float* __restrict__ bias,
                                                 float* __restrict__ outC, int N)
{
    const float* A;
    float* C;
    switch (which) {
        case 0:  A = g_objfeas; C = g_h1;  break;
        case 1:  A = g_h1;      C = outC;  break;
        case 2:  A = g_pooled;  C = g_h2;  break;
        default: A = g_h2;      C = outC;  break;
    }
    __shared__ float As[512];
    int row = blockIdx.x;
    for (int k = threadIdx.x; k < 512; k += 128) As[k] = A[(size_t)row*512 + k];
    __syncthreads();
    int n = blockIdx.y*128 + threadIdx.x;
    if (n < N) {
        float acc = bias[n];
        #pragma unroll 8
        for (int k = 0; k < 512; k++) acc += As[k]*W[(size_t)k*N + n];
        C[(size_t)row*N + n] = acc;
    }
}

// 9) labels: obj_category[:, 2:4] flattened, as float
__global__ void labels_kernel(const int* __restrict__ cat, float* __restrict__ out)
{
    int i = threadIdx.x;   // 32
    out[i] = (float)cat[(i >> 1)*4 + 2 + (i & 1)];
}

// ---------------------------------------------------------------------------
extern "C" void kernel_launch(void* const* d_in, const int* in_sizes, int n_in,
                              void* d_out, int out_size)
{
    (void)in_sizes; (void)n_in; (void)out_size;
    const float* x       = (const float*)d_in[0];
    const float* boxes   = (const float*)d_in[1];
    const int*   cat     = (const int*)  d_in[2];
    const float* conv5_w = (const float*)d_in[3];
    const float* re_w    = (const float*)d_in[4];
    const float* re_b    = (const float*)d_in[5];
    const float* oc1_w   = (const float*)d_in[6];
    const float* oc1_b   = (const float*)d_in[7];
    const float* oc2_w   = (const float*)d_in[8];
    const float* oc2_b   = (const float*)d_in[9];
    const float* pr1_w   = (const float*)d_in[10];
    const float* pr1_b   = (const float*)d_in[11];
    const float* pr2_w   = (const float*)d_in[12];
    const float* pr2_b   = (const float*)d_in[13];
    float* out = (float*)d_out;

    taps_kernel<<<1, 512>>>(boxes);
    pool_kernel<<<dim3(128, 4), 256>>>(x);
    gemm1_kernel<<<dim3(36, 4), 256>>>(conv5_w);            // 4608x2048x512
    gemm2_kernel<<<dim3(4, 4, SPLITK), 256>>>(re_w);        // 512x4608x512 splitK=9
    reduce_relu_kernel<<<1024, 256>>>(re_b);
    regmean_kernel<<<128, 256>>>();
    post2_kernel<<<96, 256>>>();
    head_gemm<<<dim3(32, 4), 128>>>(0, oc1_w, oc1_b, nullptr,     512);
    head_gemm<<<dim3(32, 3), 128>>>(1, oc2_w, oc2_b, out + 2784,  301);
    head_gemm<<<dim3(16, 4), 128>>>(2, pr1_w, pr1_b, nullptr,     512);
    head_gemm<<<dim3(16, 2), 128>>>(3, pr2_w, pr2_b, out,         174);
    labels_kernel<<<1, 32>>>(cat, out + 12416);
}